// round 8
// baseline (speedup 1.0000x reference)
#include <cuda_runtime.h>
#include <cuda_bf16.h>

// Partials layout (16 floats per block):
// dice blocks: [0..3] probsum, [4..7] intersect, [8..11] count, [12..15]=0
// bce  blocks: [0..11]=0, [12]=B (Σ t*(s-x)), [13]=A (Σ s), [14]=C (Σ t*x), [15]=pos_cnt
#define NBLK      1184
#define DICE_BLK  848            // ~ traffic ratio 98.3MB : 39.3MB
#define NACC      16

__device__ float g_part[NBLK * NACC];
__device__ unsigned int g_ticket;   // zero-init at load; reset by last block each run

__device__ __forceinline__ void block_partials(float* v) {
    #pragma unroll
    for (int i = 0; i < NACC; i++) {
        #pragma unroll
        for (int off = 16; off > 0; off >>= 1)
            v[i] += __shfl_down_sync(0xffffffffu, v[i], off);
    }
    __shared__ float sm[8 * NACC];
    const int warp = threadIdx.x >> 5;
    const int lane = threadIdx.x & 31;
    if (lane == 0) {
        #pragma unroll
        for (int i = 0; i < NACC; i++) sm[warp * NACC + i] = v[i];
    }
    __syncthreads();
    if (threadIdx.x < NACC) {
        float t = 0.0f;
        #pragma unroll
        for (int w = 0; w < 8; w++) t += sm[w * NACC + threadIdx.x];
        g_part[blockIdx.x * NACC + threadIdx.x] = t;
    }
}

// Accumulate one dice group (4 voxels) given its preloaded registers.
struct DiceAcc {
    float ps0, ps1, ps2, ps3, is0, is1, is2, is3;
    unsigned int cpk;
};
__device__ __forceinline__ void dice_group(const float4& x0, const float4& x1,
                                           const float4& x2, const float4& x3,
                                           const int4& km, DiceAcc& a) {
    const float a0[4] = {x0.x, x0.y, x0.z, x0.w};
    const float a1[4] = {x1.x, x1.y, x1.z, x1.w};
    const float a2[4] = {x2.x, x2.y, x2.z, x2.w};
    const float a3[4] = {x3.x, x3.y, x3.z, x3.w};
    const int   kk[4] = {km.x, km.y, km.z, km.w};
    #pragma unroll
    for (int j = 0; j < 4; j++) {
        const float e0 = __expf(a0[j]);
        const float e1 = __expf(a1[j]);
        const float e2 = __expf(a2[j]);
        const float e3 = __expf(a3[j]);
        const float inv = __fdividef(1.0f, e0 + e1 + e2 + e3);
        const float p0 = e0 * inv, p1 = e1 * inv, p2 = e2 * inv, p3 = e3 * inv;
        a.ps0 += p0; a.ps1 += p1; a.ps2 += p2; a.ps3 += p3;
        const int k = kk[j];
        if (k == 0) a.is0 += p0;
        if (k == 1) a.is1 += p1;
        if (k == 2) a.is2 += p2;
        if (k == 3) a.is3 += p3;
        a.cpk += 1u << (k << 3);
    }
}

__device__ __forceinline__ void bce_group(const float4& xv, const int4& tv,
                                          float& A, float& B, float& C, int& ip) {
    const float xa[4] = {xv.x, xv.y, xv.z, xv.w};
    const int   ta[4] = {tv.x, tv.y, tv.z, tv.w};
    #pragma unroll
    for (int j = 0; j < 4; j++) {
        const float xi = xa[j];
        const int   ti = ta[j];
        const float t  = __expf(-fabsf(xi));
        const float s  = fmaxf(xi, 0.0f) + __logf(1.0f + t);
        const float tf = (float)ti;
        A += s;
        B += tf * (s - xi);
        C += tf * xi;
        ip += ti;
    }
}

__global__ void __launch_bounds__(256)
k_fused(const float* __restrict__ seg, const int* __restrict__ segmask,
        const float* __restrict__ edge, const int* __restrict__ edgemask,
        int spatial, int ngroups,            // ngroups = nvox/4
        float* __restrict__ out, int nvox) {
    float acc[NACC];
    #pragma unroll
    for (int i = 0; i < NACC; i++) acc[i] = 0.0f;

    if (blockIdx.x < DICE_BLK) {
        // ================= DICE (unroll x2 for MLP) =================
        DiceAcc a = {0,0,0,0, 0,0,0,0, 0u};
        const int stride = DICE_BLK * blockDim.x;
        int g = blockIdx.x * blockDim.x + threadIdx.x;

        for (; g + stride < ngroups; g += 2 * stride) {
            const int vA = g * 4;
            const int vB = (g + stride) * 4;
            const float* pA = seg + vA + ((vA >= spatial) ? 3 * (size_t)spatial : 0);
            const float* pB = seg + vB + ((vB >= spatial) ? 3 * (size_t)spatial : 0);

            // 10 independent 16B loads, issued before any compute.
            const float4 xA0 = *(const float4*)(pA);
            const float4 xA1 = *(const float4*)(pA + (size_t)spatial);
            const float4 xA2 = *(const float4*)(pA + 2 * (size_t)spatial);
            const float4 xA3 = *(const float4*)(pA + 3 * (size_t)spatial);
            const float4 xB0 = *(const float4*)(pB);
            const float4 xB1 = *(const float4*)(pB + (size_t)spatial);
            const float4 xB2 = *(const float4*)(pB + 2 * (size_t)spatial);
            const float4 xB3 = *(const float4*)(pB + 3 * (size_t)spatial);
            const int4  kmA  = *(const int4*)(segmask + vA);
            const int4  kmB  = *(const int4*)(segmask + vB);

            dice_group(xA0, xA1, xA2, xA3, kmA, a);
            dice_group(xB0, xB1, xB2, xB3, kmB, a);
        }
        for (; g < ngroups; g += stride) {
            const int v = g * 4;
            const float* p = seg + v + ((v >= spatial) ? 3 * (size_t)spatial : 0);
            const float4 x0 = *(const float4*)(p);
            const float4 x1 = *(const float4*)(p + (size_t)spatial);
            const float4 x2 = *(const float4*)(p + 2 * (size_t)spatial);
            const float4 x3 = *(const float4*)(p + 3 * (size_t)spatial);
            const int4  km  = *(const int4*)(segmask + v);
            dice_group(x0, x1, x2, x3, km, a);
        }
        acc[0] = a.ps0; acc[1] = a.ps1; acc[2] = a.ps2; acc[3] = a.ps3;
        acc[4] = a.is0; acc[5] = a.is1; acc[6] = a.is2; acc[7] = a.is3;
        acc[8]  = (float)(a.cpk & 0xFFu);
        acc[9]  = (float)((a.cpk >> 8) & 0xFFu);
        acc[10] = (float)((a.cpk >> 16) & 0xFFu);
        acc[11] = (float)((a.cpk >> 24) & 0xFFu);
    } else {
        // ================= BCE (unroll x4 for MLP) =================
        float A = 0, B = 0, C = 0;
        int ip = 0;
        const int bce_blocks = NBLK - DICE_BLK;
        const int stride = bce_blocks * blockDim.x;
        int g = (blockIdx.x - DICE_BLK) * blockDim.x + threadIdx.x;

        for (; g + 3 * stride < ngroups; g += 4 * stride) {
            const int v0 = g * 4;
            const int v1 = (g + stride) * 4;
            const int v2 = (g + 2 * stride) * 4;
            const int v3 = (g + 3 * stride) * 4;
            const float4 x0 = *(const float4*)(edge + v0);
            const float4 x1 = *(const float4*)(edge + v1);
            const float4 x2 = *(const float4*)(edge + v2);
            const float4 x3 = *(const float4*)(edge + v3);
            const int4   t0 = *(const int4*)(edgemask + v0);
            const int4   t1 = *(const int4*)(edgemask + v1);
            const int4   t2 = *(const int4*)(edgemask + v2);
            const int4   t3 = *(const int4*)(edgemask + v3);
            bce_group(x0, t0, A, B, C, ip);
            bce_group(x1, t1, A, B, C, ip);
            bce_group(x2, t2, A, B, C, ip);
            bce_group(x3, t3, A, B, C, ip);
        }
        for (; g < ngroups; g += stride) {
            const int v = g * 4;
            const float4 xv = *(const float4*)(edge + v);
            const int4   tv = *(const int4*)(edgemask + v);
            bce_group(xv, tv, A, B, C, ip);
        }
        acc[12] = B; acc[13] = A; acc[14] = C; acc[15] = (float)ip;
    }

    block_partials(acc);

    // ---- Last block performs the final reduction ----
    __threadfence();
    __shared__ unsigned int s_is_last;
    if (threadIdx.x == 0) {
        const unsigned int old = atomicAdd(&g_ticket, 1u);
        s_is_last = (old == gridDim.x - 1) ? 1u : 0u;
    }
    __syncthreads();
    if (!s_is_last) return;

    __shared__ double s_tot[NACC];
    {
        const int warp = threadIdx.x >> 5;
        const int lane = threadIdx.x & 31;
        #pragma unroll
        for (int h = 0; h < 2; h++) {
            const int a = warp + h * 8;
            double t = 0.0;
            for (int blk = lane; blk < NBLK; blk += 32)
                t += (double)g_part[blk * NACC + a];
            #pragma unroll
            for (int off = 16; off > 0; off >>= 1)
                t += __shfl_down_sync(0xffffffffu, t, off);
            if (lane == 0) s_tot[a] = t;
        }
    }
    __syncthreads();

    if (threadIdx.x == 0) {
        const double SMOOTH = 1e-5;
        double dice_sum = 0.0;
        #pragma unroll
        for (int c = 0; c < 4; c++) {
            const double P = s_tot[c];
            const double I = s_tot[4 + c];
            const double K = s_tot[8 + c];
            dice_sum += (2.0 * I + SMOOTH) / (P + K + SMOOTH);
        }
        out[0] = (float)(1.0 - dice_sum / 4.0);

        const double B = s_tot[12], A = s_tot[13], C = s_tot[14];
        const double pos = s_tot[15];
        const double neg = (double)nvox - pos;
        const double sum = pos + neg;
        const double wsum = (neg / sum) * B + (pos / sum) * (A - B - C);
        out[1] = (float)(wsum / (double)nvox);

        g_ticket = 0;   // reset for next graph replay (deterministic)
    }
}

extern "C" void kernel_launch(void* const* d_in, const int* in_sizes, int n_in,
                              void* d_out, int out_size) {
    const float* segin    = (const float*)d_in[0];
    const float* edgein   = (const float*)d_in[1];
    const int*   segmask  = (const int*)d_in[2];
    const int*   edgemask = (const int*)d_in[3];
    float* out = (float*)d_out;

    const int nvox = in_sizes[2];         // n * d*h*w == 4,915,200
    const int sp   = nvox / 2;            // per-batch spatial (n = 2)

    k_fused<<<NBLK, 256>>>(segin, segmask, edgein, edgemask,
                           sp, nvox / 4, out, nvox);
}